// round 4
// baseline (speedup 1.0000x reference)
#include <cuda_runtime.h>
#include <cstdint>

#define NB 8
#define NC 19
#define NH 512
#define NW 512
#define HW (NH * NW)            // 262144 = 2^18
#define NPIX (NB * HW)          // 2097152

// g_acc layout:
//  [0..18]  probs_sum_c   [19..37] inter_c
//  [38] focal_sum  [39] nll_sum  [40] slp_sum  [41] bnll_sum
//  [42..60] count_c
#define NACC 61

__device__ float g_acc[NACC];
__device__ unsigned int g_ticket;
__device__ unsigned char g_diff[HW];
__device__ float g_pt[NPIX];          // per-pixel p_target scratch (8 MB)

// ---------------------------------------------------------------------------
// Vectorized: 4 columns per thread via int4. Also zeroes g_acc / g_ticket.
__global__ void diff_kernel(const int* __restrict__ tgt) {
    int idx = blockIdx.x * blockDim.x + threadIdx.x;    // over HW/4
    if (blockIdx.x == 0) {
        if (threadIdx.x < NACC) g_acc[threadIdx.x] = 0.0f;
        if (threadIdx.x == 0) g_ticket = 0u;
    }
    if (idx >= HW / 4) return;
    int h = idx >> 7;                                    // 128 int4 per row
    uchar4 d = make_uchar4(0, 0, 0, 0);
    if (h >= 1 && h <= NH - 2) {
        const int4* t4 = (const int4*)tgt;
        int rowbase = idx;                               // in int4 units
#pragma unroll
        for (int b = 0; b < NB; b++) {
            int base = b * (HW / 4) + rowbase;
            int4 a = __ldg(t4 + base - NW / 4);
            int4 m = __ldg(t4 + base);
            int4 q = __ldg(t4 + base + NW / 4);
            d.x |= (unsigned char)((a.x != m.x) | (a.x != q.x));
            d.y |= (unsigned char)((a.y != m.y) | (a.y != q.y));
            d.z |= (unsigned char)((a.z != m.z) | (a.z != q.z));
            d.w |= (unsigned char)((a.w != m.w) | (a.w != q.w));
        }
    }
    ((uchar4*)g_diff)[idx] = d;
}

// ---------------------------------------------------------------------------
__device__ __forceinline__ float warp_sum(float v) {
#pragma unroll
    for (int o = 16; o; o >>= 1) v += __shfl_down_sync(0xffffffffu, v, o);
    return v;
}

// ---------------------------------------------------------------------------
// Hot loop: softmax statistics only. No one-hot work, no atomics in the loop.
__global__ __launch_bounds__(256) void main_kernel(const float* __restrict__ in,
                                                   const int* __restrict__ tgt) {
    __shared__ float s_blk[NACC];
    if (threadIdx.x < NACC) s_blk[threadIdx.x] = 0.0f;
    __syncthreads();

    const int hw = blockIdx.x * 256 + threadIdx.x;   // NTHREADS == HW
    const int h = hw >> 9;
    const int w = hw & (NW - 1);

    float bm = 0.0f;
    if (h >= 1 && h <= NH - 2 && w >= 1 && w <= NW - 2) {
        bm = (float)(g_diff[hw - 1] | g_diff[hw] | g_diff[hw + 1]);
    }

    float denom[NC];
#pragma unroll
    for (int c = 0; c < NC; c++) denom[c] = 0.0f;
    float a_focal = 0.0f, a_nll = 0.0f, a_slp = 0.0f, a_bnll = 0.0f;

#pragma unroll 1
    for (int b = 0; b < NB; b++) {
        const int t = tgt[b * HW + hw];
        const float* base = in + (size_t)b * (NC * HW) + hw;

        float x[NC];
#pragma unroll
        for (int c = 0; c < NC; c++) x[c] = __ldg(base + (size_t)c * HW);
        const float xt = __ldg(base + (size_t)t * HW);   // L1 hit

        float s0 = 0.f, s1 = 0.f, s2 = 0.f, s3 = 0.f;
#pragma unroll
        for (int c = 0; c < NC; c++) {
            if ((c & 3) == 0) s0 += x[c];
            else if ((c & 3) == 1) s1 += x[c];
            else if ((c & 3) == 2) s2 += x[c];
            else s3 += x[c];
        }
        const float sumx = (s0 + s1) + (s2 + s3);

        float z0 = 0.f, z1 = 0.f, z2 = 0.f, z3 = 0.f;
#pragma unroll
        for (int c = 0; c < NC; c++) {
            x[c] = __expf(x[c]);
            if ((c & 3) == 0) z0 += x[c];
            else if ((c & 3) == 1) z1 += x[c];
            else if ((c & 3) == 2) z2 += x[c];
            else z3 += x[c];
        }
        const float Z = (z0 + z1) + (z2 + z3);

        const float invZ = __fdividef(1.0f, Z);
        const float logZ = __logf(Z);
        const float nll = logZ - xt;
        const float pt = __expf(xt) * invZ;

#pragma unroll
        for (int c = 0; c < NC; c++) denom[c] = fmaf(x[c], invZ, denom[c]);

        const float om = 1.0f - pt;
        a_focal = fmaf(om * om, nll, a_focal);
        a_nll += nll;
        a_slp += fmaf(-(float)NC, logZ, sumx);
        a_bnll = fmaf(nll, bm, a_bnll);

        g_pt[b * HW + hw] = pt;          // scratch for hist kernel
    }

    const int lane = threadIdx.x & 31;
#pragma unroll
    for (int c = 0; c < NC; c++) {
        float v = warp_sum(denom[c]);
        if (lane == 0) atomicAdd(&s_blk[c], v);
    }
    {
        float v = warp_sum(a_focal);
        if (lane == 0) atomicAdd(&s_blk[38], v);
        v = warp_sum(a_nll);
        if (lane == 0) atomicAdd(&s_blk[39], v);
        v = warp_sum(a_slp);
        if (lane == 0) atomicAdd(&s_blk[40], v);
        v = warp_sum(a_bnll);
        if (lane == 0) atomicAdd(&s_blk[41], v);
    }
    __syncthreads();
    if (threadIdx.x < NACC) {
        float v = s_blk[threadIdx.x];
        if (v != 0.0f) atomicAdd(&g_acc[threadIdx.x], v);
    }
}

// ---------------------------------------------------------------------------
// inter_c / count_c accumulation + fused finalize (ticketed last block).
#define HIST_BLOCKS 512
#define HIST_THREADS 256
#define HIST_STRIDE (HIST_BLOCKS * HIST_THREADS)        // 131072
#define HIST_ITERS (NPIX / HIST_STRIDE)                 // 16

__global__ __launch_bounds__(HIST_THREADS) void hist_kernel(const int* __restrict__ tgt,
                                                            float* __restrict__ out) {
    __shared__ float s_blk[2 * NC];
    __shared__ bool s_last;
    if (threadIdx.x < 2 * NC) s_blk[threadIdx.x] = 0.0f;
    __syncthreads();

    const int tid = blockIdx.x * HIST_THREADS + threadIdx.x;

    float inter[NC];
    float cnt[NC];
#pragma unroll
    for (int c = 0; c < NC; c++) { inter[c] = 0.0f; cnt[c] = 0.0f; }

#pragma unroll 1
    for (int k = 0; k < HIST_ITERS; k++) {
        const int p = tid + k * HIST_STRIDE;
        const int t = __ldg(tgt + p);
        const float pt = __ldg(g_pt + p);
#pragma unroll
        for (int c = 0; c < NC; c++) {
            if (c == t) { inter[c] += pt; cnt[c] += 1.0f; }
        }
    }

    const int lane = threadIdx.x & 31;
#pragma unroll
    for (int c = 0; c < NC; c++) {
        float v = warp_sum(inter[c]);
        if (lane == 0) atomicAdd(&s_blk[c], v);
        v = warp_sum(cnt[c]);
        if (lane == 0) atomicAdd(&s_blk[NC + c], v);
    }
    __syncthreads();
    if (threadIdx.x < NC) atomicAdd(&g_acc[NC + threadIdx.x], s_blk[threadIdx.x]);
    else if (threadIdx.x < 2 * NC) atomicAdd(&g_acc[42 + threadIdx.x - NC], s_blk[threadIdx.x]);

    // --- ticketed finalize: last block computes the 5 outputs ---
    __threadfence();
    __syncthreads();
    if (threadIdx.x == 0) {
        s_last = (atomicAdd(&g_ticket, 1u) == HIST_BLOCKS - 1);
    }
    __syncthreads();
    if (s_last && threadIdx.x < 32) {
        const float Ninv = 1.0f / (float)NPIX;
        float ps = (lane < NC) ? g_acc[lane] : 0.0f;          // probs sum
        float it = (lane < NC) ? g_acc[NC + lane] : 0.0f;     // inter
        float cn = (lane < NC) ? g_acc[42 + lane] : 0.0f;     // count
        float d = 0.0f;
        if (lane < NC) d = 1.0f - (2.0f * it + 1e-5f) / (ps + cn + 1e-5f);
        d = warp_sum(d);
        if (lane == 0) {
            float dice = d / (float)NC;
            float focal = g_acc[38] * Ninv;
            float nll_sum = g_acc[39];
            float slp_sum = g_acc[40];
            float ce = (0.9f * nll_sum - 0.1f * slp_sum / (float)NC) * Ninv;
            float boundary = (nll_sum + 0.5f * g_acc[41]) * Ninv;
            out[0] = focal;
            out[1] = dice;
            out[2] = ce;
            out[3] = boundary;
            out[4] = focal + dice + ce + boundary;
        }
    }
}

// ---------------------------------------------------------------------------
extern "C" void kernel_launch(void* const* d_in, const int* in_sizes, int n_in,
                              void* d_out, int out_size) {
    const float* inputs = (const float*)d_in[0];
    const int* targets = (const int*)d_in[1];
    float* out = (float*)d_out;

    diff_kernel<<<(HW / 4) / 256, 256>>>(targets);
    main_kernel<<<HW / 256, 256>>>(inputs, targets);
    hist_kernel<<<HIST_BLOCKS, HIST_THREADS>>>(targets, out);
}

// round 5
// speedup vs baseline: 1.6911x; 1.6911x over previous
#include <cuda_runtime.h>
#include <cstdint>

#define NB 8
#define NC 19
#define NH 512
#define NW 512
#define HW (NH * NW)            // 262144
#define NPIX (NB * HW)          // 2097152
#define NPAIR (HW / 2)          // 131072 threads, each handles 2 pixels x 8 batches

// g_acc: [0..18] probs_sum_c, [19..37] inter_c, [38] focal [39] nll [40] slp [41] bnll
#define NACC 42

__device__ float g_acc[NACC];         // zero-init; self-cleaned by last main block
__device__ int g_cnt[NC];             // target histogram (from diff_kernel)
__device__ unsigned int g_ticket;     // main-kernel completion ticket
__device__ unsigned char g_diff[HW];

// ---------------------------------------------------------------------------
// Vectorized row-diff + full target histogram (reads each target once for hist).
__global__ __launch_bounds__(256) void diff_kernel(const int* __restrict__ tgt) {
    __shared__ int s_hist[NC];
    if (threadIdx.x < NC) s_hist[threadIdx.x] = 0;
    __syncthreads();

    const int idx = blockIdx.x * 256 + threadIdx.x;     // over HW/4
    const int h = idx >> 7;                             // 128 int4 per row
    const bool interior = (h >= 1) && (h <= NH - 2);
    const int4* t4 = (const int4*)tgt;

    uchar4 d = make_uchar4(0, 0, 0, 0);
#pragma unroll
    for (int b = 0; b < NB; b++) {
        int base = b * (HW / 4) + idx;
        int4 m = __ldg(t4 + base);
        atomicAdd(&s_hist[m.x], 1);
        atomicAdd(&s_hist[m.y], 1);
        atomicAdd(&s_hist[m.z], 1);
        atomicAdd(&s_hist[m.w], 1);
        if (interior) {
            int4 a = __ldg(t4 + base - NW / 4);
            int4 q = __ldg(t4 + base + NW / 4);
            d.x |= (unsigned char)((a.x != m.x) | (a.x != q.x));
            d.y |= (unsigned char)((a.y != m.y) | (a.y != q.y));
            d.z |= (unsigned char)((a.z != m.z) | (a.z != q.z));
            d.w |= (unsigned char)((a.w != m.w) | (a.w != q.w));
        }
    }
    ((uchar4*)g_diff)[idx] = d;

    __syncthreads();
    if (threadIdx.x < NC) atomicAdd(&g_cnt[threadIdx.x], s_hist[threadIdx.x]);
}

// ---------------------------------------------------------------------------
__device__ __forceinline__ float warp_sum(float v) {
#pragma unroll
    for (int o = 16; o; o >>= 1) v += __shfl_down_sync(0xffffffffu, v, o);
    return v;
}

// ---------------------------------------------------------------------------
#define MAIN_BLOCKS (NPAIR / 256)   // 512

__global__ __launch_bounds__(256) void main_kernel(const float* __restrict__ in,
                                                   const int* __restrict__ tgt,
                                                   float* __restrict__ out) {
    __shared__ float s_int[8][NC];      // per-warp inter bins
    __shared__ float s_blk[NACC];
    __shared__ bool s_last;
    {
        int t = threadIdx.x;
        if (t < NACC) s_blk[t] = 0.0f;
        if (t < 8 * NC) ((float*)s_int)[t] = 0.0f;
    }
    __syncthreads();

    const int tidg = blockIdx.x * 256 + threadIdx.x;    // pair index
    const int wid = threadIdx.x >> 5;
    const int lane = threadIdx.x & 31;
    const int hw0 = 2 * tidg;
    const int h = hw0 >> 9;
    const int w0 = hw0 & (NW - 1);

    // boundary flags for both pixels (loop-invariant)
    float bm0 = 0.0f, bm1 = 0.0f;
    if (h >= 1 && h <= NH - 2) {
        unsigned char dm = g_diff[hw0];
        unsigned char dp = g_diff[hw0 + 1];
        if (w0 >= 1 && w0 <= NW - 2)
            bm0 = (float)(g_diff[hw0 - 1] | dm | dp);
        if (w0 + 1 <= NW - 2)
            bm1 = (float)(dm | dp | g_diff[hw0 + 2]);
    }

    const float2* in2 = (const float2*)in;
    const int2* tgt2 = (const int2*)tgt;

    float denom[NC];
#pragma unroll
    for (int c = 0; c < NC; c++) denom[c] = 0.0f;
    float a_focal = 0.0f, a_nll = 0.0f, a_slp = 0.0f, a_bnll = 0.0f;

#pragma unroll 1
    for (int b = 0; b < NB; b++) {
        const int2 tt = __ldg(tgt2 + b * (HW / 2) + tidg);
        const int t0 = tt.x, t1 = tt.y;
        const float2* base = in2 + (size_t)b * (NC * (HW / 2)) + tidg;

        // load 19 float2 (front-batched), select target logits via SEL (no gather)
        float2 x[NC];
        float xt0 = 0.0f, xt1 = 0.0f;
#pragma unroll
        for (int c = 0; c < NC; c++) {
            x[c] = __ldg(base + (size_t)c * (HW / 2));
            xt0 = (c == t0) ? x[c].x : xt0;
            xt1 = (c == t1) ? x[c].y : xt1;
        }

        // logit sums (2 chains per pixel)
        float sA0 = 0.f, sB0 = 0.f, sA1 = 0.f, sB1 = 0.f;
#pragma unroll
        for (int c = 0; c < NC; c++) {
            if (c & 1) { sB0 += x[c].x; sB1 += x[c].y; }
            else       { sA0 += x[c].x; sA1 += x[c].y; }
        }
        const float sumx0 = sA0 + sB0, sumx1 = sA1 + sB1;

        // exponentials + partition functions (2 chains per pixel)
        float zA0 = 0.f, zB0 = 0.f, zA1 = 0.f, zB1 = 0.f;
#pragma unroll
        for (int c = 0; c < NC; c++) {
            x[c].x = __expf(x[c].x);
            x[c].y = __expf(x[c].y);
            if (c & 1) { zB0 += x[c].x; zB1 += x[c].y; }
            else       { zA0 += x[c].x; zA1 += x[c].y; }
        }
        const float Z0 = zA0 + zB0, Z1 = zA1 + zB1;

        const float invZ0 = __fdividef(1.0f, Z0);
        const float invZ1 = __fdividef(1.0f, Z1);
        const float logZ0 = __logf(Z0);
        const float logZ1 = __logf(Z1);
        const float nll0 = logZ0 - xt0;
        const float nll1 = logZ1 - xt1;
        const float pt0 = __expf(xt0) * invZ0;
        const float pt1 = __expf(xt1) * invZ1;

        // per-class prob sums (both pixels into one scalar accumulator)
#pragma unroll
        for (int c = 0; c < NC; c++) {
            denom[c] = fmaf(x[c].x, invZ0, fmaf(x[c].y, invZ1, denom[c]));
        }

        const float om0 = 1.0f - pt0, om1 = 1.0f - pt1;
        a_focal = fmaf(om0 * om0, nll0, fmaf(om1 * om1, nll1, a_focal));
        a_nll += nll0 + nll1;
        a_slp += (sumx0 + sumx1) - (float)NC * (logZ0 + logZ1);
        a_bnll = fmaf(nll0, bm0, fmaf(nll1, bm1, a_bnll));

        // one-hot inter accumulation: per-warp shared bins (intra-warp conflicts only)
        atomicAdd(&s_int[wid][t0], pt0);
        atomicAdd(&s_int[wid][t1], pt1);
    }

    // --- block reduction ---
#pragma unroll
    for (int c = 0; c < NC; c++) {
        float v = warp_sum(denom[c]);
        if (lane == 0) atomicAdd(&s_blk[c], v);
    }
    {
        float v = warp_sum(a_focal);
        if (lane == 0) atomicAdd(&s_blk[38], v);
        v = warp_sum(a_nll);
        if (lane == 0) atomicAdd(&s_blk[39], v);
        v = warp_sum(a_slp);
        if (lane == 0) atomicAdd(&s_blk[40], v);
        v = warp_sum(a_bnll);
        if (lane == 0) atomicAdd(&s_blk[41], v);
    }
    __syncthreads();

    if (threadIdx.x < NC) {
        // inter: sum the 8 per-warp bins
        float vi = 0.0f;
#pragma unroll
        for (int wsel = 0; wsel < 8; wsel++) vi += s_int[wsel][threadIdx.x];
        atomicAdd(&g_acc[NC + threadIdx.x], vi);
    }
    if (threadIdx.x < NACC) {
        float v = s_blk[threadIdx.x];
        if (threadIdx.x < NC || threadIdx.x >= 38) atomicAdd(&g_acc[threadIdx.x], v);
    }

    // --- ticketed finalize + state cleanup (graph-replay safe) ---
    __threadfence();
    __syncthreads();
    if (threadIdx.x == 0)
        s_last = (atomicAdd(&g_ticket, 1u) == MAIN_BLOCKS - 1);
    __syncthreads();

    if (s_last && threadIdx.x < 32) {
        const float Ninv = 1.0f / (float)NPIX;
        float ps = (lane < NC) ? g_acc[lane] : 0.0f;
        float it = (lane < NC) ? g_acc[NC + lane] : 0.0f;
        float cn = (lane < NC) ? (float)g_cnt[lane] : 0.0f;
        float d = 0.0f;
        if (lane < NC) d = 1.0f - (2.0f * it + 1e-5f) / (ps + cn + 1e-5f);
        d = warp_sum(d);
        if (lane == 0) {
            float dice = d / (float)NC;
            float focal = g_acc[38] * Ninv;
            float nll_sum = g_acc[39];
            float slp_sum = g_acc[40];
            float ce = (0.9f * nll_sum - 0.1f * slp_sum / (float)NC) * Ninv;
            float boundary = (nll_sum + 0.5f * g_acc[41]) * Ninv;
            out[0] = focal;
            out[1] = dice;
            out[2] = ce;
            out[3] = boundary;
            out[4] = focal + dice + ce + boundary;
        }
        // reset state for the next graph replay
        if (lane < NACC) g_acc[lane] = 0.0f;
        if (lane >= NACC && lane < NACC - NC + 32) { /* no-op filler */ }
        if (lane < NC) g_cnt[lane] = 0;
        if (lane == 0) g_ticket = 0u;
        if (lane + 32 < NACC) g_acc[lane + 32] = 0.0f;
    }
}

// ---------------------------------------------------------------------------
extern "C" void kernel_launch(void* const* d_in, const int* in_sizes, int n_in,
                              void* d_out, int out_size) {
    const float* inputs = (const float*)d_in[0];
    const int* targets = (const int*)d_in[1];
    float* out = (float*)d_out;

    diff_kernel<<<(HW / 4) / 256, 256>>>(targets);
    main_kernel<<<MAIN_BLOCKS, 256>>>(inputs, targets, out);
}

// round 6
// speedup vs baseline: 1.6992x; 1.0048x over previous
#include <cuda_runtime.h>
#include <cstdint>

#define NB 8
#define NC 19
#define NH 512
#define NW 512
#define HW (NH * NW)            // 262144
#define NPIX (NB * HW)          // 2097152
#define NPAIR (HW / 2)          // 131072 pixel pairs
#define NCH 10                  // classes per lane-half (half1: 9 real + 1 dummy)

// g_acc: [0..18] probs_sum_c, [19..37] inter_c, [38] focal [39] nll [40] slp [41] bnll
#define NACC 42

__device__ float g_acc[NACC];
__device__ int g_cnt[NC];
__device__ unsigned int g_ticket;
__device__ unsigned char g_diff[HW];

// ---------------------------------------------------------------------------
// Row-diff + target histogram with per-thread private smem bins (no atomics
// in the hot loop).
#define DB 128
#define DG ((HW / 4) / DB)      // 512 blocks

__global__ __launch_bounds__(DB) void diff_kernel(const int* __restrict__ tgt) {
    __shared__ unsigned int s_h[DB][NC];
#pragma unroll
    for (int c = 0; c < NC; c++) s_h[threadIdx.x][c] = 0u;

    const int idx = blockIdx.x * DB + threadIdx.x;      // over HW/4
    const int h = idx >> 7;                             // 128 int4 per row
    const bool interior = (h >= 1) && (h <= NH - 2);
    const int4* t4 = (const int4*)tgt;

    uchar4 d = make_uchar4(0, 0, 0, 0);
#pragma unroll
    for (int b = 0; b < NB; b++) {
        int base = b * (HW / 4) + idx;
        int4 m = __ldg(t4 + base);
        s_h[threadIdx.x][m.x]++;
        s_h[threadIdx.x][m.y]++;
        s_h[threadIdx.x][m.z]++;
        s_h[threadIdx.x][m.w]++;
        if (interior) {
            int4 a = __ldg(t4 + base - NW / 4);
            int4 q = __ldg(t4 + base + NW / 4);
            d.x |= (unsigned char)((a.x != m.x) | (a.x != q.x));
            d.y |= (unsigned char)((a.y != m.y) | (a.y != q.y));
            d.z |= (unsigned char)((a.z != m.z) | (a.z != q.z));
            d.w |= (unsigned char)((a.w != m.w) | (a.w != q.w));
        }
    }
    ((uchar4*)g_diff)[idx] = d;

    __syncthreads();
    if (threadIdx.x < NC) {
        unsigned int s = 0;
#pragma unroll 8
        for (int r = 0; r < DB; r++) s += s_h[r][threadIdx.x];
        atomicAdd(&g_cnt[threadIdx.x], (int)s);
    }
}

// ---------------------------------------------------------------------------
__device__ __forceinline__ float warp_sum(float v) {
#pragma unroll
    for (int o = 16; o; o >>= 1) v += __shfl_down_sync(0xffffffffu, v, o);
    return v;
}

// ---------------------------------------------------------------------------
// Class-split main kernel: lane pairs (even,odd) share a pixel pair.
// Even lane: classes 0..9; odd lane: classes 10..18 (+dummy).
#define MAIN_BLOCKS (HW / 256)   // 1024; 2 threads per pixel pair

__global__ __launch_bounds__(256) void main_kernel(const float* __restrict__ in,
                                                   const int* __restrict__ tgt,
                                                   float* __restrict__ out) {
    __shared__ float s_int[8][NC];      // per-warp inter bins
    __shared__ float s_blk[NACC];
    __shared__ bool s_last;
    {
        int t = threadIdx.x;
        if (t < NACC) s_blk[t] = 0.0f;
        if (t < 8 * NC) ((float*)s_int)[t] = 0.0f;
    }
    __syncthreads();

    const unsigned FULL = 0xffffffffu;
    const int tid = blockIdx.x * 256 + threadIdx.x;
    const int pi = tid >> 1;            // pair index
    const int half = tid & 1;
    const int cbase = half * NCH;       // 0 or 10
    const int wid = threadIdx.x >> 5;
    const int lane = threadIdx.x & 31;

    const int hw0 = 2 * pi;
    const int h = hw0 >> 9;
    const int w0 = hw0 & (NW - 1);

    float bm0 = 0.0f, bm1 = 0.0f;
    if (h >= 1 && h <= NH - 2) {
        unsigned char dm = g_diff[hw0];
        unsigned char dp = g_diff[hw0 + 1];
        if (w0 >= 1) bm0 = (float)(g_diff[hw0 - 1] | dm | dp);
        if (w0 + 1 <= NW - 2) bm1 = (float)(dm | dp | g_diff[hw0 + 2]);
    }

    const float2* in2 = (const float2*)in;
    const int2* tgt2 = (const int2*)tgt;

    float denom[NCH];
#pragma unroll
    for (int c = 0; c < NCH; c++) denom[c] = 0.0f;
    float a_focal = 0.0f, a_nll = 0.0f, a_slp = 0.0f, a_bnll = 0.0f;

#pragma unroll 1
    for (int b = 0; b < NB; b++) {
        const int2 tt = __ldg(tgt2 + b * (HW / 2) + pi);
        const int t0 = tt.x, t1 = tt.y;
        const float2* base = in2 + (size_t)b * (NC * (HW / 2)) + pi;

        // 10 float2 loads (last is a dummy re-read of class 18 for half1)
        float2 x[NCH];
#pragma unroll
        for (int c2 = 0; c2 < NCH; c2++) {
            int lc = cbase + c2;
            if (c2 == NCH - 1) lc = half ? 18 : 9;
            x[c2] = __ldg(base + (size_t)lc * (HW / 2));
        }

        // local sums / target select / exp
        float sx0 = 0.f, sx1 = 0.f, z0 = 0.f, z1 = 0.f, xl0 = 0.f, xl1 = 0.f;
#pragma unroll
        for (int c2 = 0; c2 < NCH; c2++) {
            float vx = x[c2].x, vy = x[c2].y;
            const int cc = cbase + c2;          // ==19 for half1 dummy -> never matches t
            float ex = __expf(vx);
            float ey = __expf(vy);
            if (c2 == NCH - 1 && half) { vx = 0.f; vy = 0.f; ex = 0.f; ey = 0.f; }
            sx0 += vx; sx1 += vy;
            xl0 = (cc == t0) ? vx : xl0;
            xl1 = (cc == t1) ? vy : xl1;
            z0 += ex; z1 += ey;
            x[c2].x = ex; x[c2].y = ey;
        }

        // combine halves (lane pairs)
        const float Z0 = z0 + __shfl_xor_sync(FULL, z0, 1);
        const float Z1 = z1 + __shfl_xor_sync(FULL, z1, 1);
        const float sumx = (sx0 + sx1) + __shfl_xor_sync(FULL, sx0 + sx1, 1);
        const float xt0 = xl0 + __shfl_xor_sync(FULL, xl0, 1);
        const float xt1 = xl1 + __shfl_xor_sync(FULL, xl1, 1);

        const float invZ0 = __fdividef(1.0f, Z0);
        const float invZ1 = __fdividef(1.0f, Z1);

#pragma unroll
        for (int c2 = 0; c2 < NCH; c2++) {
            denom[c2] = fmaf(x[c2].x, invZ0, fmaf(x[c2].y, invZ1, denom[c2]));
        }

        if (!half) {        // even lanes own the scalar losses
            const float logZ0 = __logf(Z0);
            const float logZ1 = __logf(Z1);
            const float nll0 = logZ0 - xt0;
            const float nll1 = logZ1 - xt1;
            const float pt0 = __expf(xt0) * invZ0;
            const float pt1 = __expf(xt1) * invZ1;
            const float om0 = 1.0f - pt0, om1 = 1.0f - pt1;
            a_focal = fmaf(om0 * om0, nll0, fmaf(om1 * om1, nll1, a_focal));
            a_nll += nll0 + nll1;
            a_slp += sumx - (float)NC * (logZ0 + logZ1);
            a_bnll = fmaf(nll0, bm0, fmaf(nll1, bm1, a_bnll));
            atomicAdd(&s_int[wid][t0], pt0);
            atomicAdd(&s_int[wid][t1], pt1);
        }
    }

    // --- denom reduction: parity-preserving pairwise shuffle ---
#pragma unroll
    for (int c2 = 0; c2 < NCH; c2++) {
        float v = denom[c2];
        v += __shfl_down_sync(FULL, v, 16);
        v += __shfl_down_sync(FULL, v, 8);
        v += __shfl_down_sync(FULL, v, 4);
        v += __shfl_down_sync(FULL, v, 2);
        if (lane == 0) atomicAdd(&s_blk[c2], v);                    // classes 0..9
        else if (lane == 1 && c2 < NCH - 1) atomicAdd(&s_blk[NCH + c2], v); // 10..18
    }
    {
        float v = warp_sum(a_focal);
        if (lane == 0) atomicAdd(&s_blk[38], v);
        v = warp_sum(a_nll);
        if (lane == 0) atomicAdd(&s_blk[39], v);
        v = warp_sum(a_slp);
        if (lane == 0) atomicAdd(&s_blk[40], v);
        v = warp_sum(a_bnll);
        if (lane == 0) atomicAdd(&s_blk[41], v);
    }
    __syncthreads();

    if (threadIdx.x < NC) {
        float vi = 0.0f;
#pragma unroll
        for (int wsel = 0; wsel < 8; wsel++) vi += s_int[wsel][threadIdx.x];
        atomicAdd(&g_acc[NC + threadIdx.x], vi);
    }
    if (threadIdx.x < NACC && (threadIdx.x < NC || threadIdx.x >= 38)) {
        atomicAdd(&g_acc[threadIdx.x], s_blk[threadIdx.x]);
    }

    // --- ticketed finalize + state cleanup (graph-replay safe) ---
    __threadfence();
    __syncthreads();
    if (threadIdx.x == 0)
        s_last = (atomicAdd(&g_ticket, 1u) == MAIN_BLOCKS - 1);
    __syncthreads();

    if (s_last && threadIdx.x < 32) {
        const float Ninv = 1.0f / (float)NPIX;
        float ps = (lane < NC) ? g_acc[lane] : 0.0f;
        float it = (lane < NC) ? g_acc[NC + lane] : 0.0f;
        float cn = (lane < NC) ? (float)g_cnt[lane] : 0.0f;
        float d = 0.0f;
        if (lane < NC) d = 1.0f - (2.0f * it + 1e-5f) / (ps + cn + 1e-5f);
        d = warp_sum(d);
        if (lane == 0) {
            float dice = d / (float)NC;
            float focal = g_acc[38] * Ninv;
            float nll_sum = g_acc[39];
            float slp_sum = g_acc[40];
            float ce = (0.9f * nll_sum - 0.1f * slp_sum / (float)NC) * Ninv;
            float boundary = (nll_sum + 0.5f * g_acc[41]) * Ninv;
            out[0] = focal;
            out[1] = dice;
            out[2] = ce;
            out[3] = boundary;
            out[4] = focal + dice + ce + boundary;
        }
        // reset device state for the next graph replay
        if (lane < NACC) g_acc[lane] = 0.0f;
        if (lane + 32 < NACC) g_acc[lane + 32] = 0.0f;
        if (lane < NC) g_cnt[lane] = 0;
        if (lane == 0) g_ticket = 0u;
    }
}

// ---------------------------------------------------------------------------
extern "C" void kernel_launch(void* const* d_in, const int* in_sizes, int n_in,
                              void* d_out, int out_size) {
    const float* inputs = (const float*)d_in[0];
    const int* targets = (const int*)d_in[1];
    float* out = (float*)d_out;

    diff_kernel<<<DG, DB>>>(targets);
    main_kernel<<<MAIN_BLOCKS, 256>>>(inputs, targets, out);
}